// round 5
// baseline (speedup 1.0000x reference)
#include <cuda_runtime.h>

#define Hh 64
#define Tt 512
#define Bt 4096
#define BPB 28      // batches per block, grid = 147
#define NBT 14      // batches per 128-thread group
#define NTHREADS 256
#define TX 32

typedef unsigned long long ull;

__device__ __forceinline__ ull ffma2(ull a, ull b, ull c) {
    ull d;
    asm("fma.rn.f32x2 %0, %1, %2, %3;" : "=l"(d) : "l"(a), "l"(b), "l"(c));
    return d;
}
__device__ __forceinline__ float2 unpk(ull v) {
    float2 f;
    asm("mov.b64 {%0, %1}, %2;" : "=f"(f.x), "=f"(f.y) : "l"(v));
    return f;
}
__device__ __forceinline__ void grpbar(int id) {
    asm volatile("bar.sync %0, 128;" :: "r"(id) : "memory");
}
__device__ __forceinline__ float sigmoid_f(float x) {
    x = fminf(fmaxf(x, -30.f), 30.f);             // FMNMX: alu pipe
    float e = __expf(-x);
    return __fdividef(1.f, 1.f + e);
}
__device__ __forceinline__ float tanh_f(float x) {
    x = fminf(fmaxf(x, -15.f), 15.f);
    float e = __expf(-2.f * x);
    return __fdividef(1.f - e, 1.f + e);
}

extern "C" __global__ void __launch_bounds__(NTHREADS, 1)
gru_persistent_kernel(const float* __restrict__ x,
                      const float* __restrict__ W_ih,
                      const float* __restrict__ W_hh,
                      const float* __restrict__ b_ih,
                      const float* __restrict__ b_hh,
                      const float* __restrict__ W_out,
                      const float* __restrict__ b_out,
                      float* __restrict__ out)
{
    extern __shared__ float sm[];
    float* hb = sm;                          // [2][BPB][64]
    float* xs = hb + 2 * BPB * Hh;           // [BPB][TX]

    const int tid   = threadIdx.x;
    const int khalf = tid & 1;               // k-half: 0 -> k 0..31, 1 -> k 32..63
    const int j     = (tid >> 1) & 63;       // hidden index
    const int grp   = tid >> 7;              // 0..1, 128-thread group = 14 batches
    const int lt    = tid & 127;
    const int bBase = blockIdx.x * BPB;

    // ---- All W_hh weights for (j, khalf) cached in registers ----
    ull wr[16], wz[16], wn[16];              // 16 k-pairs each
    {
        const float* rr = W_hh + (0 * Hh + j) * Hh + khalf * 32;
        const float* rz = W_hh + (1 * Hh + j) * Hh + khalf * 32;
        const float* rn = W_hh + (2 * Hh + j) * Hh + khalf * 32;
        #pragma unroll
        for (int kp = 0; kp < 16; ++kp) {
            wr[kp] = *reinterpret_cast<const ull*>(rr + 2 * kp);
            wz[kp] = *reinterpret_cast<const ull*>(rz + 2 * kp);
            wn[kp] = *reinterpret_cast<const ull*>(rn + 2 * kp);
        }
    }

    for (int idx = tid; idx < BPB * Hh; idx += NTHREADS)
        hb[idx] = 0.f;

    const float wir = W_ih[j];
    const float wiz = W_ih[Hh + j];
    const float win = W_ih[2 * Hh + j];
    const float cr  = b_ih[j]          + b_hh[j];
    const float cz  = b_ih[Hh + j]     + b_hh[Hh + j];
    const float cnx = b_ih[2 * Hh + j];
    const float cnh = b_hh[2 * Hh + j];

    __syncthreads();                         // h0 visible

    // Each lane runs the epilogue for 7 of the group's 14 batches.
    float hprev[7];
    #pragma unroll
    for (int i = 0; i < 7; ++i) hprev[i] = 0.f;

    int cur = 0;
    const int bar = grp + 1;

    for (int t = 0; t < Tt; ++t) {
        if ((t & (TX - 1)) == 0) {
            // Group stages x for its 14 batches: 448 floats / 128 threads.
            #pragma unroll
            for (int r = 0; r < 4; ++r) {
                int idx = lt + r * 128;
                if (idx < NBT * TX) {
                    int bi = idx >> 5;
                    int tt2 = idx & 31;
                    int bl = grp * NBT + bi;
                    int bg = bBase + bl;
                    xs[bl * TX + tt2] = (bg < Bt) ? x[bg * Tt + t + tt2] : 0.f;
                }
            }
            grpbar(bar);
        }

        // Partial sums over this thread's 32-k half, all 14 batches.
        ull ar[NBT], az[NBT], an[NBT];
        #pragma unroll
        for (int i = 0; i < NBT; ++i) { ar[i] = 0ull; az[i] = 0ull; an[i] = 0ull; }

        const float* hg = hb + cur * BPB * Hh + grp * NBT * Hh + khalf * 32;

        #pragma unroll
        for (int kq = 0; kq < 8; ++kq) {     // 4 k per iter (2 pairs)
            #pragma unroll
            for (int i = 0; i < NBT; ++i) {
                ulonglong2 h2 = *reinterpret_cast<const ulonglong2*>(hg + i * Hh + 4 * kq);
                ar[i] = ffma2(h2.x, wr[2 * kq],     ar[i]);
                ar[i] = ffma2(h2.y, wr[2 * kq + 1], ar[i]);
                az[i] = ffma2(h2.x, wz[2 * kq],     az[i]);
                az[i] = ffma2(h2.y, wz[2 * kq + 1], az[i]);
                an[i] = ffma2(h2.x, wn[2 * kq],     an[i]);
                an[i] = ffma2(h2.y, wn[2 * kq + 1], an[i]);
            }
        }

        // Combine halves: horizontal add + butterfly with partner lane (lane^1).
        float tr[NBT], tz[NBT], tn[NBT];
        #pragma unroll
        for (int i = 0; i < NBT; ++i) {
            float2 p;
            float s;
            p = unpk(ar[i]); s = p.x + p.y;
            tr[i] = s + __shfl_xor_sync(0xffffffffu, s, 1);
            p = unpk(az[i]); s = p.x + p.y;
            tz[i] = s + __shfl_xor_sync(0xffffffffu, s, 1);
            p = unpk(an[i]); s = p.x + p.y;
            tn[i] = s + __shfl_xor_sync(0xffffffffu, s, 1);
        }

        const int tt = t & (TX - 1);
        float* hnext = hb + (cur ^ 1) * BPB * Hh;
        const bool hi = (khalf != 0);

        // khalf=0 lane: batches 0..6 ; khalf=1 lane: batches 7..13.
        #pragma unroll
        for (int i = 0; i < 7; ++i) {
            float sr = hi ? tr[i + 7] : tr[i];
            float sz = hi ? tz[i + 7] : tz[i];
            float sn = hi ? tn[i + 7] : tn[i];
            int bl = grp * NBT + khalf * 7 + i;
            float xv = xs[bl * TX + tt];
            float r  = sigmoid_f(fmaf(xv, wir, sr + cr));
            float z  = sigmoid_f(fmaf(xv, wiz, sz + cz));
            float n  = tanh_f(fmaf(xv, win, cnx) + r * (sn + cnh));
            float hn = fmaf(z, hprev[i] - n, n);
            hprev[i] = hn;
            hnext[bl * Hh + j] = hn;
        }
        grpbar(bar);
        cur ^= 1;
    }

    __syncthreads();

    if (tid < BPB && bBase + tid < Bt) {
        const float* hl = hb + cur * BPB * Hh + tid * Hh;
        float s = b_out[0];
        #pragma unroll
        for (int k = 0; k < Hh; ++k)
            s = fmaf(hl[k], W_out[k], s);
        out[bBase + tid] = s;
    }
}

extern "C" void kernel_launch(void* const* d_in, const int* in_sizes, int n_in,
                              void* d_out, int out_size)
{
    const float* x     = (const float*)d_in[0];
    const float* W_ih  = (const float*)d_in[1];
    const float* W_hh  = (const float*)d_in[2];
    const float* b_ih  = (const float*)d_in[3];
    const float* b_hh  = (const float*)d_in[4];
    const float* W_out = (const float*)d_in[5];
    const float* b_out = (const float*)d_in[6];
    float* out = (float*)d_out;

    const size_t smem = (size_t)(2 * BPB * Hh + BPB * TX) * sizeof(float);
    cudaFuncSetAttribute(gru_persistent_kernel,
                         cudaFuncAttributeMaxDynamicSharedMemorySize, (int)smem);

    const int grid = (Bt + BPB - 1) / BPB;   // 147
    gru_persistent_kernel<<<grid, NTHREADS, smem>>>(
        x, W_ih, W_hh, b_ih, b_hh, W_out, b_out, out);
}

// round 6
// speedup vs baseline: 1.0810x; 1.0810x over previous
#include <cuda_runtime.h>

#define Hh 64
#define Tt 512
#define Bt 4096
#define BPB 30      // batches per block, grid = 137 (last block: 16 real batches)
#define NBT 5       // batches per 64-thread group
#define NGRP 6
#define NTHREADS 384
#define TX 32       // x timesteps staged per chunk

typedef unsigned long long ull;

__device__ __forceinline__ ull ffma2(ull a, ull b, ull c) {
    ull d;
    asm("fma.rn.f32x2 %0, %1, %2, %3;" : "=l"(d) : "l"(a), "l"(b), "l"(c));
    return d;
}
__device__ __forceinline__ float2 unpk(ull v) {
    float2 f;
    asm("mov.b64 {%0, %1}, %2;" : "=f"(f.x), "=f"(f.y) : "l"(v));
    return f;
}
__device__ __forceinline__ void grpbar(int id) {
    asm volatile("bar.sync %0, 64;" :: "r"(id) : "memory");
}
__device__ __forceinline__ float sigmoid_f(float x) {
    x = fminf(fmaxf(x, -30.f), 30.f);
    float e = __expf(-x);
    return __fdividef(1.f, 1.f + e);
}
__device__ __forceinline__ float tanh_f(float x) {
    x = fminf(fmaxf(x, -15.f), 15.f);
    float e = __expf(-2.f * x);
    return __fdividef(1.f - e, 1.f + e);
}

extern "C" __global__ void __launch_bounds__(NTHREADS, 1)
gru_persistent_kernel(const float* __restrict__ x,
                      const float* __restrict__ W_ih,
                      const float* __restrict__ W_hh,
                      const float* __restrict__ b_ih,
                      const float* __restrict__ b_hh,
                      const float* __restrict__ W_out,
                      const float* __restrict__ b_out,
                      float* __restrict__ out)
{
    extern __shared__ float sm[];
    // Weights packed as [gate][kq][j] float4 = {W[4kq..4kq+3][j]}; 48KB
    ulonglong2* W4 = reinterpret_cast<ulonglong2*>(sm);
    float* hb = sm + 3 * 16 * Hh * 4;        // [2][BPB][64]
    float* xs = hb + 2 * BPB * Hh;           // [BPB][TX]

    const int tid = threadIdx.x;
    const int j = tid & 63;
    const int g = tid >> 6;                  // 0..5 group (2 warps)
    const int lt = tid & 63;
    const int bBase = blockIdx.x * BPB;

    // Prepack W_hh: W4f[gate*1024 + kq*64 + j] = {W_hh[(gate*64+j)*64 + 4kq+0..3]}
    {
        float4* W4f = reinterpret_cast<float4*>(sm);
        for (int idx = tid; idx < 3 * 16 * Hh; idx += NTHREADS) {
            int gate = idx >> 10;
            int rem  = idx & 1023;
            int kq   = rem >> 6;
            int jj   = rem & 63;
            const float* row = W_hh + (gate * Hh + jj) * Hh + 4 * kq;
            W4f[idx] = make_float4(row[0], row[1], row[2], row[3]);
        }
    }
    for (int idx = tid; idx < BPB * Hh; idx += NTHREADS)
        hb[idx] = 0.f;

    const float wir = W_ih[j];
    const float wiz = W_ih[Hh + j];
    const float win = W_ih[2 * Hh + j];
    const float cr  = b_ih[j]          + b_hh[j];
    const float cz  = b_ih[Hh + j]     + b_hh[Hh + j];
    const float cnx = b_ih[2 * Hh + j];
    const float cnh = b_hh[2 * Hh + j];

    __syncthreads();                          // publish weights + h0

    const ulonglong2* Wr = W4 + 0 * 16 * Hh;
    const ulonglong2* Wz = W4 + 1 * 16 * Hh;
    const ulonglong2* Wn = W4 + 2 * 16 * Hh;

    float hprev[NBT];
    #pragma unroll
    for (int i = 0; i < NBT; ++i) hprev[i] = 0.f;

    int cur = 0;
    const int bar = g + 1;

    for (int t = 0; t < Tt; ++t) {
        if ((t & (TX - 1)) == 0) {
            // Stage x for this group's NBT batches: NBT*TX=160 floats / 64 threads.
            #pragma unroll
            for (int r = 0; r < (NBT * TX + 63) / 64; ++r) {
                int idx = lt + r * 64;
                if (idx < NBT * TX) {
                    int bi = idx >> 5;
                    int tt2 = idx & 31;
                    int bl = g * NBT + bi;
                    int bg = bBase + bl;
                    xs[bl * TX + tt2] = (bg < Bt) ? x[bg * Tt + t + tt2] : 0.f;
                }
            }
            grpbar(bar);
        }

        ull acc_r[NBT], acc_z[NBT], acc_n[NBT];
        #pragma unroll
        for (int i = 0; i < NBT; ++i) { acc_r[i] = 0ull; acc_z[i] = 0ull; acc_n[i] = 0ull; }

        const float* hcur = hb + cur * BPB * Hh + (g * NBT) * Hh;

        #pragma unroll
        for (int kq = 0; kq < 16; ++kq) {
            ulonglong2 wr = Wr[kq * Hh + j];
            ulonglong2 wz = Wz[kq * Hh + j];
            ulonglong2 wn = Wn[kq * Hh + j];
            #pragma unroll
            for (int i = 0; i < NBT; ++i) {
                ulonglong2 h2 = *reinterpret_cast<const ulonglong2*>(hcur + i * Hh + 4 * kq);
                acc_r[i] = ffma2(h2.x, wr.x, acc_r[i]);
                acc_r[i] = ffma2(h2.y, wr.y, acc_r[i]);
                acc_z[i] = ffma2(h2.x, wz.x, acc_z[i]);
                acc_z[i] = ffma2(h2.y, wz.y, acc_z[i]);
                acc_n[i] = ffma2(h2.x, wn.x, acc_n[i]);
                acc_n[i] = ffma2(h2.y, wn.y, acc_n[i]);
            }
        }

        const int tt = t & (TX - 1);
        float* hnext = hb + (cur ^ 1) * BPB * Hh;
        #pragma unroll
        for (int i = 0; i < NBT; ++i) {
            const int bl = g * NBT + i;
            float2 pr = unpk(acc_r[i]);
            float2 pz = unpk(acc_z[i]);
            float2 pn = unpk(acc_n[i]);
            float ar = pr.x + pr.y;
            float az = pz.x + pz.y;
            float an = pn.x + pn.y;
            float xv = xs[bl * TX + tt];
            float r  = sigmoid_f(fmaf(xv, wir, ar + cr));
            float z  = sigmoid_f(fmaf(xv, wiz, az + cz));
            float n  = tanh_f(fmaf(xv, win, cnx) + r * (an + cnh));
            float hn = fmaf(z, hprev[i] - n, n);
            hprev[i] = hn;
            hnext[bl * Hh + j] = hn;
        }
        grpbar(bar);
        cur ^= 1;
    }

    __syncthreads();

    if (tid < BPB && bBase + tid < Bt) {
        const float* hl = hb + cur * BPB * Hh + tid * Hh;
        float s = b_out[0];
        #pragma unroll
        for (int k = 0; k < Hh; ++k)
            s = fmaf(hl[k], W_out[k], s);
        out[bBase + tid] = s;
    }
}

extern "C" void kernel_launch(void* const* d_in, const int* in_sizes, int n_in,
                              void* d_out, int out_size)
{
    const float* x     = (const float*)d_in[0];
    const float* W_ih  = (const float*)d_in[1];
    const float* W_hh  = (const float*)d_in[2];
    const float* b_ih  = (const float*)d_in[3];
    const float* b_hh  = (const float*)d_in[4];
    const float* W_out = (const float*)d_in[5];
    const float* b_out = (const float*)d_in[6];
    float* out = (float*)d_out;

    const size_t smem = (size_t)(3 * 16 * Hh * 4 + 2 * BPB * Hh + BPB * TX) * sizeof(float);
    cudaFuncSetAttribute(gru_persistent_kernel,
                         cudaFuncAttributeMaxDynamicSharedMemorySize, (int)smem);

    const int grid = (Bt + BPB - 1) / BPB;   // 137
    gru_persistent_kernel<<<grid, NTHREADS, smem>>>(
        x, W_ih, W_hh, b_ih, b_hh, W_out, b_out, out);
}